// round 11
// baseline (speedup 1.0000x reference)
#include <cuda_runtime.h>

// Problem constants (fixed by the reference)
#define B_     4
#define N_     4096
#define E_     128
#define CACHE_ 32
#define NK_    4
#define CE_    32      // channels per unit (E / NK)
#define M_     128     // N / CACHE
#define BNE_   (B_*N_*E_)
#define NW_    2       // warps per block
#define CPW_   16      // channels per warp per unit
#define KP_    8       // packed channel pairs per warp per unit

// Inter-layer scratch (device globals: no allocation in kernel_launch)
__device__ float g_x [BNE_];
__device__ float g_xa[BNE_];

typedef unsigned long long u64;

__device__ __forceinline__ float tanh_fast(float x) {
    float y;
    asm("tanh.approx.f32 %0, %1;" : "=f"(y) : "f"(x));
    return y;
}
__device__ __forceinline__ u64 pk(float lo, float hi) {
    u64 r; asm("mov.b64 %0, {%1, %2};" : "=l"(r) : "f"(lo), "f"(hi)); return r;
}
__device__ __forceinline__ void upk(u64 x, float& lo, float& hi) {
    asm("mov.b64 {%0, %1}, %2;" : "=f"(lo), "=f"(hi) : "l"(x));
}
__device__ __forceinline__ u64 fma2(u64 a, u64 b, u64 c) {
    u64 d; asm("fma.rn.f32x2 %0, %1, %2, %3;" : "=l"(d) : "l"(a), "l"(b), "l"(c)); return d;
}
__device__ __forceinline__ u64 mul2(u64 a, u64 b) {
    u64 d; asm("mul.rn.f32x2 %0, %1, %2;" : "=l"(d) : "l"(a), "l"(b)); return d;
}
__device__ __forceinline__ u64 add2(u64 a, u64 b) {
    u64 d; asm("add.rn.f32x2 %0, %1, %2;" : "=l"(d) : "l"(a), "l"(b)); return d;
}

// TWO units (same b,g; n = 2a and 2a+1) per 64-thread block. Warp w owns
// channels [w*16, w*16+16) of BOTH units — doubles per-warp independent work
// so each warp hides its own latency. Rescaled state u=(xi/2)/0.9^j,
// v=(xa/2)/0.9^j. Linear-split partial running dots per warp per unit:
// X2=(Ax_w,Bx_w), A2=(Aa_w,Ba_w); sim = Ax_tot[lane] + shfl(Bx_tot, j).
// Row-j state comes from a per-warp-per-unit smem mirror (lane j+1 publishes).
// X' = .9X+.09A+.01S with P2 = .9X+.09A precomputed off the critical path.
// One __syncthreads per step covers both units.
__global__ void __launch_bounds__(64, 7)
ncn_layer(const float* __restrict__ X, const float* __restrict__ XA,
          const float* __restrict__ W,         // 256 floats: Wi[4][32], Wj[4][32]
          float* __restrict__ YX, float* __restrict__ YA,
          int s)                                // group-index stride (0 or 1)
{
    __shared__ float tile[CACHE_][64 + 1];      // 32 rows x 64 channels (+pad)
    __shared__ u64 ebuf[2][2][NW_][CACHE_];     // [parity][unit][warp][lane]
    __shared__ __align__(16) u64 sW4[2][CE_];   // per unit: (Wi2,Wj2) interleaved
    __shared__ __align__(16) u64 mir[2][2][NW_][KP_];  // [parity][unit][warp]

    const int t    = threadIdx.x;
    const int w    = t >> 5;                    // warp in block (0/1)
    const int lane = t & 31;                    // row-in-group
    const int blk  = blockIdx.x;                // 0 .. 1023
    const int a    = blk & 1;                   // unit-pair index (n = 2a, 2a+1)
    const int g    = (blk >> 1) & (M_ - 1);
    const int b    = blk >> 8;

    // weights for both units
    if (t < 32) {
        int unit = t >> 4;                      // 0/1
        int pr   = t & 15;                      // pair index
        int c    = (2 * a + unit) * CE_ + 2 * pr;
        sW4[unit][2 * pr]     = pk(W[c],      W[c + 1]);
        sW4[unit][2 * pr + 1] = pk(W[E_ + c], W[E_ + c + 1]);
    }

    const long long bBase   = (long long)b * N_ * E_;
    const int colBase = a * 64;                 // first global channel of pair
    const int cw = w * CPW_;                    // warp's channel offset in unit
    const int kw = cw >> 1;                     // warp's first weight pair
    const ulonglong2* sWvA = reinterpret_cast<const ulonglong2*>(sW4[0]);
    const ulonglong2* sWvB = reinterpret_cast<const ulonglong2*>(sW4[1]);

    u64 uA[KP_], vA[KP_], uB[KP_], vB[KP_];

    // ---- gather xi: warp w loads rows [w*16,w*16+16), 64 ch/row coalesced ----
    #pragma unroll
    for (int r = 0; r < CPW_; ++r) {
        int rr  = cw + r;
        int row = ((g + rr * s) & (M_ - 1)) * CACHE_ + rr;
        const float* src = X + bBase + (long long)row * E_ + colBase;
        tile[rr][lane]      = src[lane];
        tile[rr][lane + 32] = src[lane + 32];
    }
    __syncthreads();
    #pragma unroll
    for (int k = 0; k < KP_; ++k) {
        uA[k] = pk(0.5f * tile[lane][cw + 2 * k],      0.5f * tile[lane][cw + 2 * k + 1]);
        uB[k] = pk(0.5f * tile[lane][32 + cw + 2 * k], 0.5f * tile[lane][32 + cw + 2 * k + 1]);
    }
    __syncthreads();

    // ---- gather xa ----
    #pragma unroll
    for (int r = 0; r < CPW_; ++r) {
        int rr  = cw + r;
        int row = ((g + rr * s) & (M_ - 1)) * CACHE_ + rr;
        const float* src = XA + bBase + (long long)row * E_ + colBase;
        tile[rr][lane]      = src[lane];
        tile[rr][lane + 32] = src[lane + 32];
    }
    __syncthreads();
    #pragma unroll
    for (int k = 0; k < KP_; ++k) {
        vA[k] = pk(0.5f * tile[lane][cw + 2 * k],      0.5f * tile[lane][cw + 2 * k + 1]);
        vB[k] = pk(0.5f * tile[lane][32 + cw + 2 * k], 0.5f * tile[lane][32 + cw + 2 * k + 1]);
    }

    const u64 K09  = pk(0.9f,  0.9f);
    const u64 K01  = pk(0.1f,  0.1f);
    const u64 K009 = pk(0.09f, 0.09f);
    const u64 K001 = pk(0.01f, 0.01f);
    const u64 K2   = pk(2.f, 2.f);
    const u64 Z    = pk(0.f, 0.f);

    // ---- initial partials per unit: X2=(Ax_w,Bx_w), A2=(Aa_w,Ba_w) ----
    u64 X2A, A2A, P2A, X2B, A2B, P2B;
    {
        u64 axA = Z, bxA = Z, aaA = Z, baA = Z;
        u64 axB = Z, bxB = Z, aaB = Z, baB = Z;
        #pragma unroll
        for (int k = 0; k < KP_; ++k) {
            ulonglong2 wA = sWvA[kw + k], wB = sWvB[kw + k];
            axA = fma2(uA[k], wA.x, axA); bxA = fma2(uA[k], wA.y, bxA);
            aaA = fma2(vA[k], wA.x, aaA); baA = fma2(vA[k], wA.y, baA);
            axB = fma2(uB[k], wB.x, axB); bxB = fma2(uB[k], wB.y, bxB);
            aaB = fma2(vB[k], wB.x, aaB); baB = fma2(vB[k], wB.y, baB);
        }
        float l, h, p, q;
        upk(axA, l, h); upk(bxA, p, q); X2A = mul2(pk(l + h, p + q), K2);
        upk(aaA, l, h); upk(baA, p, q); A2A = mul2(pk(l + h, p + q), K2);
        upk(axB, l, h); upk(bxB, p, q); X2B = mul2(pk(l + h, p + q), K2);
        upk(aaB, l, h); upk(baB, p, q); A2B = mul2(pk(l + h, p + q), K2);
        P2A = fma2(X2A, K09, mul2(A2A, K009));
        P2B = fma2(X2B, K09, mul2(A2B, K009));
    }
    ebuf[0][0][w][lane] = X2A;
    ebuf[0][1][w][lane] = X2B;
    if (lane == 0) {
        #pragma unroll
        for (int k2 = 0; k2 < KP_ / 2; ++k2) {
            ulonglong2 ta; ta.x = uA[2 * k2]; ta.y = uA[2 * k2 + 1];
            ulonglong2 tb; tb.x = uB[2 * k2]; tb.y = uB[2 * k2 + 1];
            *reinterpret_cast<ulonglong2*>(&mir[0][0][w][2 * k2]) = ta;
            *reinterpret_cast<ulonglong2*>(&mir[0][1][w][2 * k2]) = tb;
        }
    }
    __syncthreads();

    float sc = 1.0f;                  // 0.9^j
    float cj = 0.05f / 0.9f;          // 0.05 / 0.9^(j+1)

    // ---- 32-step recurrence ----
    #pragma unroll 1
    for (int j = 0; j < CACHE_; ++j) {
        const int p = j & 1;

        // row-j pre-update state per unit (uniform broadcast LDS.128)
        ulonglong2 ujA[KP_ / 2], ujB[KP_ / 2];
        #pragma unroll
        for (int k2 = 0; k2 < KP_ / 2; ++k2) {
            ujA[k2] = *reinterpret_cast<const ulonglong2*>(&mir[p][0][w][2 * k2]);
            ujB[k2] = *reinterpret_cast<const ulonglong2*>(&mir[p][1][w][2 * k2]);
        }

        // sims
        u64 totA = add2(X2A, ebuf[p][0][1 - w][lane]);
        u64 totB = add2(X2B, ebuf[p][1][1 - w][lane]);
        float AxA, BxA, AxB, BxB;
        upk(totA, AxA, BxA);
        upk(totB, AxB, BxB);
        float simA = AxA + __shfl_sync(0xffffffffu, BxA, j);
        float simB = AxB + __shfl_sync(0xffffffffu, BxB, j);

        u64 simA2 = pk(simA, simA), simB2 = pk(simB, simB);
        u64 s2 = pk(sc, sc), c2 = pk(cj, cj);
        u64 SAa = Z, SBa = Z, DAa = Z, DBa = Z;
        u64 SAb = Z, SBb = Z, DAb = Z, DBb = Z;
        #pragma unroll
        for (int k = 0; k < KP_; ++k) {
            u64 ujAk = (k & 1) ? ujA[k >> 1].y : ujA[k >> 1].x;
            u64 ujBk = (k & 1) ? ujB[k >> 1].y : ujB[k >> 1].x;
            u64 TA = mul2(s2, fma2(simA2, ujAk, uA[k]));
            u64 TB = mul2(s2, fma2(simB2, ujBk, uB[k]));
            float a0, a1, b0, b1;
            upk(TA, a0, a1); upk(TB, b0, b1);
            u64 FA = pk(tanh_fast(a0), tanh_fast(a1));
            u64 FB = pk(tanh_fast(b0), tanh_fast(b1));
            ulonglong2 wA = sWvA[kw + k], wB = sWvB[kw + k];
            if (k & 1) {
                SBa = fma2(FA, wA.x, SBa); DBa = fma2(FA, wA.y, DBa);
                SBb = fma2(FB, wB.x, SBb); DBb = fma2(FB, wB.y, DBb);
            } else {
                SAa = fma2(FA, wA.x, SAa); DAa = fma2(FA, wA.y, DAa);
                SAb = fma2(FB, wB.x, SAb); DAb = fma2(FB, wB.y, DAb);
            }
            vA[k] = fma2(c2,  FA,    vA[k]);
            uA[k] = fma2(K01, vA[k], uA[k]);
            vB[k] = fma2(c2,  FB,    vB[k]);
            uB[k] = fma2(K01, vB[k], uB[k]);
        }
        float l, h, p0, q0;
        u64 S2A, S2B;
        { u64 x = add2(SAa, SBa), y = add2(DAa, DBa);
          upk(x, l, h); upk(y, p0, q0); S2A = pk(l + h, p0 + q0); }
        { u64 x = add2(SAb, SBb), y = add2(DAb, DBb);
          upk(x, l, h); upk(y, p0, q0); S2B = pk(l + h, p0 + q0); }

        X2A = fma2(S2A, K001, P2A);
        X2B = fma2(S2B, K001, P2B);
        ebuf[p ^ 1][0][w][lane] = X2A;
        ebuf[p ^ 1][1][w][lane] = X2B;
        A2A = fma2(A2A, K09, mul2(S2A, K01));
        P2A = fma2(X2A, K09, mul2(A2A, K009));
        A2B = fma2(A2B, K09, mul2(S2B, K01));
        P2B = fma2(X2B, K09, mul2(A2B, K009));

        if (lane == j + 1) {
            #pragma unroll
            for (int k2 = 0; k2 < KP_ / 2; ++k2) {
                ulonglong2 ta; ta.x = uA[2 * k2]; ta.y = uA[2 * k2 + 1];
                ulonglong2 tb; tb.x = uB[2 * k2]; tb.y = uB[2 * k2 + 1];
                *reinterpret_cast<ulonglong2*>(&mir[p ^ 1][0][w][2 * k2]) = ta;
                *reinterpret_cast<ulonglong2*>(&mir[p ^ 1][1][w][2 * k2]) = tb;
            }
        }
        __syncthreads();                        // one bar per step, both units

        sc *= 0.9f;
        cj *= (1.0f / 0.9f);
    }

    const float fscale = 2.0f * sc;   // undo half-scale and 0.9^32 rescale

    // ---- scatter yi ----
    #pragma unroll
    for (int k = 0; k < KP_; ++k) {
        float l, h;
        upk(uA[k], l, h);
        tile[lane][cw + 2 * k]          = fscale * l;
        tile[lane][cw + 2 * k + 1]      = fscale * h;
        upk(uB[k], l, h);
        tile[lane][32 + cw + 2 * k]     = fscale * l;
        tile[lane][32 + cw + 2 * k + 1] = fscale * h;
    }
    __syncthreads();
    #pragma unroll
    for (int r = 0; r < CPW_; ++r) {
        int rr  = cw + r;
        int row = ((g + rr * s) & (M_ - 1)) * CACHE_ + rr;
        float* dst = YX + bBase + (long long)row * E_ + colBase;
        dst[lane]      = tile[rr][lane];
        dst[lane + 32] = tile[rr][lane + 32];
    }
    __syncthreads();

    // ---- scatter ya ----
    #pragma unroll
    for (int k = 0; k < KP_; ++k) {
        float l, h;
        upk(vA[k], l, h);
        tile[lane][cw + 2 * k]          = fscale * l;
        tile[lane][cw + 2 * k + 1]      = fscale * h;
        upk(vB[k], l, h);
        tile[lane][32 + cw + 2 * k]     = fscale * l;
        tile[lane][32 + cw + 2 * k + 1] = fscale * h;
    }
    __syncthreads();
    #pragma unroll
    for (int r = 0; r < CPW_; ++r) {
        int rr  = cw + r;
        int row = ((g + rr * s) & (M_ - 1)) * CACHE_ + rr;
        float* dst = YA + bBase + (long long)row * E_ + colBase;
        dst[lane]      = tile[rr][lane];
        dst[lane + 32] = tile[rr][lane + 32];
    }
}

extern "C" void kernel_launch(void* const* d_in, const int* in_sizes, int n_in,
                              void* d_out, int out_size) {
    const float* x  = (const float*)d_in[0];
    const float* xa = (const float*)d_in[1];
    const float* W  = (const float*)d_in[2];
    float* out = (float*)d_out;

    float *gx = nullptr, *gxa = nullptr;
    cudaGetSymbolAddress((void**)&gx,  g_x);
    cudaGetSymbolAddress((void**)&gxa, g_xa);

    dim3 grid(B_ * M_ * NK_ / 2);   // 1024 blocks, 2 units each
    dim3 block(64);

    // Layer 0: stage shift s = 0 (contiguous groups)
    ncn_layer<<<grid, block>>>(x, xa, W, gx, gxa, 0);
    // Layer 1: stage shift s = 1 (block = (g + o) % m), writes final output
    ncn_layer<<<grid, block>>>(gx, gxa, W + 2 * E_, out, out + BNE_, 1);
}

// round 12
// speedup vs baseline: 1.0602x; 1.0602x over previous
#include <cuda_runtime.h>

// Problem constants (fixed by the reference)
#define B_     4
#define N_     4096
#define E_     128
#define CACHE_ 32
#define NK_    4
#define CE_    32      // channels per unit (E / NK)
#define M_     128     // N / CACHE
#define BNE_   (B_*N_*E_)
#define NW_    2       // warps per unit
#define CPW_   16      // channels per warp
#define KP_    8       // packed channel pairs per warp

// Inter-layer scratch (device globals: no allocation in kernel_launch)
__device__ float g_x [BNE_];
__device__ float g_xa[BNE_];

typedef unsigned long long u64;

__device__ __forceinline__ float tanh_fast(float x) {
    float y;
    asm("tanh.approx.f32 %0, %1;" : "=f"(y) : "f"(x));
    return y;
}
__device__ __forceinline__ u64 pk(float lo, float hi) {
    u64 r; asm("mov.b64 %0, {%1, %2};" : "=l"(r) : "f"(lo), "f"(hi)); return r;
}
__device__ __forceinline__ void upk(u64 x, float& lo, float& hi) {
    asm("mov.b64 {%0, %1}, %2;" : "=f"(lo), "=f"(hi) : "l"(x));
}
__device__ __forceinline__ u64 fma2(u64 a, u64 b, u64 c) {
    u64 d; asm("fma.rn.f32x2 %0, %1, %2, %3;" : "=l"(d) : "l"(a), "l"(b), "l"(c)); return d;
}
__device__ __forceinline__ u64 mul2(u64 a, u64 b) {
    u64 d; asm("mul.rn.f32x2 %0, %1, %2;" : "=l"(d) : "l"(a), "l"(b)); return d;
}
__device__ __forceinline__ u64 add2(u64 a, u64 b) {
    u64 d; asm("add.rn.f32x2 %0, %1, %2;" : "=l"(d) : "l"(a), "l"(b)); return d;
}

// 2 warps per (b,g,n) unit (round-6 structure) + per-SM PHASE DESYNC:
// all 2048 blocks are one wave and otherwise run in lockstep, convoying the
// MUFU/FMA bursts of every step. Blocks sharing an SM are bid, bid+148, ...,
// so phase = bid/148 indexes co-resident blocks; each spins phase*150 cycles
// once at entry to smear the per-step pipe bursts across the step period.
__global__ void __launch_bounds__(64, 14)
ncn_layer(const float* __restrict__ X, const float* __restrict__ XA,
          const float* __restrict__ W,         // 256 floats: Wi[4][32], Wj[4][32]
          float* __restrict__ YX, float* __restrict__ YA,
          int s)                                // group-index stride (0 or 1)
{
    __shared__ float tile[CACHE_][CACHE_ + 1];
    __shared__ u64 ebuf[2][NW_][CACHE_];        // [parity][warp][lane] = (Ax_w,Bx_w)
    __shared__ __align__(16) u64 sWc[CE_];      // (Wi[c], Wj[c]) per channel

    const int t    = threadIdx.x;
    const int w    = t >> 5;                    // warp in block (0/1)
    const int lane = t & 31;                    // row-in-group
    const int blk  = blockIdx.x;                // 0 .. 2047
    const int n    = blk & (NK_ - 1);
    const int g    = (blk >> 2) & (M_ - 1);
    const int b    = blk >> 9;

    // ---- phase desync: stagger co-resident blocks by ~150 cyc each ----
    {
        unsigned phase = (unsigned)blk / 148u;  // 0..13 = slot on this SM
        if (phase) {
            long long lim = (long long)phase * 150;
            long long t0  = clock64();
            while (clock64() - t0 < lim) { }
        }
    }

    if (t < CE_)
        sWc[t] = pk(W[n * CE_ + t], W[E_ + n * CE_ + t]);

    const long long bBase    = (long long)b * N_ * E_;
    const long long chanBase = (long long)n * CE_ + lane;
    const int cw = w * CPW_;                    // this warp's first channel

    u64 u2[KP_], v2[KP_];

    // ---- gather xi tile: warp w loads rows [w*16, w*16+16), coalesced ----
    #pragma unroll
    for (int r = 0; r < CPW_; ++r) {
        int rr  = cw + r;
        int row = ((g + rr * s) & (M_ - 1)) * CACHE_ + rr;
        tile[rr][lane] = X[bBase + (long long)row * E_ + chanBase];
    }
    __syncthreads();
    #pragma unroll
    for (int k = 0; k < KP_; ++k)
        u2[k] = pk(0.5f * tile[lane][cw + 2 * k], 0.5f * tile[lane][cw + 2 * k + 1]);
    __syncthreads();

    // ---- gather xa tile ----
    #pragma unroll
    for (int r = 0; r < CPW_; ++r) {
        int rr  = cw + r;
        int row = ((g + rr * s) & (M_ - 1)) * CACHE_ + rr;
        tile[rr][lane] = XA[bBase + (long long)row * E_ + chanBase];
    }
    __syncthreads();
    #pragma unroll
    for (int k = 0; k < KP_; ++k)
        v2[k] = pk(0.5f * tile[lane][cw + 2 * k], 0.5f * tile[lane][cw + 2 * k + 1]);

    const u64 K09  = pk(0.9f,  0.9f);
    const u64 K01  = pk(0.1f,  0.1f);
    const u64 K009 = pk(0.09f, 0.09f);
    const u64 K001 = pk(0.01f, 0.01f);
    const u64 K2   = pk(2.f, 2.f);
    const u64 Z    = pk(0.f, 0.f);
    const ulonglong2* sWc2 = reinterpret_cast<const ulonglong2*>(sWc);

    // ---- initial partials: X2w=(Ax_w,Bx_w), A2w=(Aa_w,Ba_w), packed ----
    u64 X2w = Z, A2w = Z;
    #pragma unroll
    for (int k = 0; k < KP_; ++k) {
        ulonglong2 ww = sWc2[(cw >> 1) + k];    // (Wi,Wj) for ch c0, c1
        float x0, x1, a0, a1;
        upk(u2[k], x0, x1);
        upk(v2[k], a0, a1);
        X2w = fma2(pk(x0, x0), ww.x, X2w);
        X2w = fma2(pk(x1, x1), ww.y, X2w);
        A2w = fma2(pk(a0, a0), ww.x, A2w);
        A2w = fma2(pk(a1, a1), ww.y, A2w);
    }
    X2w = mul2(X2w, K2);                        // undo half-scale
    A2w = mul2(A2w, K2);
    u64 P2 = fma2(X2w, K09, mul2(A2w, K009));   // .9X + .09A (for step 0)
    ebuf[0][w][lane] = X2w;                     // publish for step 0
    __syncthreads();

    float sc = 1.0f;                  // 0.9^j
    float cj = 0.05f / 0.9f;          // 0.05 / 0.9^(j+1)

    // ---- 32-step recurrence ----
    #pragma unroll 1
    for (int j = 0; j < CACHE_; ++j) {
        const int p = j & 1;

        // sim = (Ax_own + Ax_other)[lane] + (Bx_w0 + Bx_w1)[j]
        u64 oth = ebuf[p][1 - w][lane];
        u64 bj0 = ebuf[p][0][j];                // broadcast LDS
        u64 bj1 = ebuf[p][1][j];
        float Axw, Bxw, oAx, oBx, j0x, j0y, j1x, j1y;
        upk(X2w, Axw, Bxw);
        upk(oth, oAx, oBx);
        upk(bj0, j0x, j0y);
        upk(bj1, j1x, j1y);
        float sim = (Axw + oAx) + (j0y + j1y);

        u64 sim2 = pk(sim, sim);
        u64 s2   = pk(sc, sc);
        u64 c2   = pk(cj, cj);
        u64 aA = Z, aB = Z, aC = Z, aD = Z;     // packed (SF,DF) partials
        #pragma unroll
        for (int k = 0; k < KP_; ++k) {
            u64 uj = __shfl_sync(0xffffffffu, u2[k], j);    // pre-update row j
            u64 T  = mul2(s2, fma2(sim2, uj, u2[k]));       // true-scale T
            float t0, t1; upk(T, t0, t1);
            float f0 = tanh_fast(t0), f1 = tanh_fast(t1);
            u64 F = pk(f0, f1);
            ulonglong2 ww = sWc2[(cw >> 1) + k];
            if (k & 1) { aB = fma2(pk(f0, f0), ww.x, aB); aD = fma2(pk(f1, f1), ww.y, aD); }
            else       { aA = fma2(pk(f0, f0), ww.x, aA); aC = fma2(pk(f1, f1), ww.y, aC); }
            v2[k] = fma2(c2,  F,     v2[k]);                // ~xa update
            u2[k] = fma2(K01, v2[k], u2[k]);                // ~xi update
        }
        u64 S2 = add2(add2(aA, aB), add2(aC, aD));          // packed (SF,DF)

        X2w = fma2(S2, K001, P2);                           // X' = .9X+.09A+.01S
        ebuf[p ^ 1][w][lane] = X2w;                         // publish (STS.64)
        A2w = fma2(A2w, K09, mul2(S2, K01));                // off-chain
        P2  = fma2(X2w, K09, mul2(A2w, K009));              // for next step
        __syncthreads();                                    // one bar per step

        sc *= 0.9f;
        cj *= (1.0f / 0.9f);
    }

    const float fscale = 2.0f * sc;   // undo half-scale and 0.9^32 rescale

    // ---- scatter yi ----
    #pragma unroll
    for (int k = 0; k < KP_; ++k) {
        float l, h; upk(u2[k], l, h);
        tile[lane][cw + 2 * k]     = fscale * l;
        tile[lane][cw + 2 * k + 1] = fscale * h;
    }
    __syncthreads();
    #pragma unroll
    for (int r = 0; r < CPW_; ++r) {
        int rr  = cw + r;
        int row = ((g + rr * s) & (M_ - 1)) * CACHE_ + rr;
        YX[bBase + (long long)row * E_ + chanBase] = tile[rr][lane];
    }
    __syncthreads();

    // ---- scatter ya ----
    #pragma unroll
    for (int k = 0; k < KP_; ++k) {
        float l, h; upk(v2[k], l, h);
        tile[lane][cw + 2 * k]     = fscale * l;
        tile[lane][cw + 2 * k + 1] = fscale * h;
    }
    __syncthreads();
    #pragma unroll
    for (int r = 0; r < CPW_; ++r) {
        int rr  = cw + r;
        int row = ((g + rr * s) & (M_ - 1)) * CACHE_ + rr;
        YA[bBase + (long long)row * E_ + chanBase] = tile[rr][lane];
    }
}

extern "C" void kernel_launch(void* const* d_in, const int* in_sizes, int n_in,
                              void* d_out, int out_size) {
    const float* x  = (const float*)d_in[0];
    const float* xa = (const float*)d_in[1];
    const float* W  = (const float*)d_in[2];
    float* out = (float*)d_out;

    float *gx = nullptr, *gxa = nullptr;
    cudaGetSymbolAddress((void**)&gx,  g_x);
    cudaGetSymbolAddress((void**)&gxa, g_xa);

    dim3 grid(B_ * M_ * NK_);   // 2048 blocks
    dim3 block(64);             // 2 warps per unit

    // Layer 0: stage shift s = 0 (contiguous groups)
    ncn_layer<<<grid, block>>>(x, xa, W, gx, gxa, 0);
    // Layer 1: stage shift s = 1 (block = (g + o) % m), writes final output
    ncn_layer<<<grid, block>>>(gx, gxa, W + 2 * E_, out, out + BNE_, 1);
}